// round 3
// baseline (speedup 1.0000x reference)
#include <cuda_runtime.h>
#include <math.h>

#define D_MODEL 1024
#define BATCH   4
#define SEQ     4096

// Scratch (allocation-free rule: __device__ globals, zero-init .bss)
__device__ __align__(256) float g_xQK[(size_t)BATCH * SEQ * D_MODEL];          //  64 MB
__device__ __align__(256) float g_S  [(size_t)BATCH * SEQ * SEQ];              // 256 MB
__device__ __align__(256) float g_av [(size_t)BATCH * SEQ * D_MODEL];          //  64 MB

// ---------------------------------------------------------------------------
// Tiled SGEMM: C = alpha * A * op(B)
//   A: [M,K] row-major.  TRANS_B=false: B [K,N] row-major.  TRANS_B=true: B [N,K] row-major (C=A*B^T).
//   Batched via blockIdx.z with element strides sA/sB/sC.
//   All dims are multiples of the tile sizes for this problem — no bounds checks.
//   BM=BN=128, BK=16, 8x8 per thread, 256 threads.
// ---------------------------------------------------------------------------
template <bool TRANS_B>
__global__ __launch_bounds__(256)
void sgemm_kernel(int M, int N, int K, float alpha,
                  const float* __restrict__ A, size_t sA,
                  const float* __restrict__ B, size_t sB,
                  float* __restrict__ C, size_t sC)
{
    constexpr int BM = 128, BN = 128, BK = 16, TM = 8, TN = 8;
    __shared__ float As[BK][BM + 4];
    __shared__ float Bs[BK][BN + 4];

    const float* Ab = A + (size_t)blockIdx.z * sA;
    const float* Bb = B + (size_t)blockIdx.z * sB;
    float*       Cb = C + (size_t)blockIdx.z * sC;

    const int bm = blockIdx.y * BM;
    const int bn = blockIdx.x * BN;
    const int tid = threadIdx.x;

    const int tx = tid & 15;   // 16 threads across N
    const int ty = tid >> 4;   // 16 threads across M

    float acc[TM][TN];
#pragma unroll
    for (int i = 0; i < TM; i++)
#pragma unroll
        for (int j = 0; j < TN; j++) acc[i][j] = 0.0f;

    for (int k0 = 0; k0 < K; k0 += BK) {
        // ---- A tile: 128 rows x 16 cols, transposed into As[k][m].
        // 512 float4 loads; 2 per thread.
#pragma unroll
        for (int i = 0; i < 2; i++) {
            int idx  = tid + i * 256;
            int row  = idx >> 2;          // 0..127
            int col  = (idx & 3) * 4;     // 0,4,8,12
            float4 a4 = *reinterpret_cast<const float4*>(
                Ab + (size_t)(bm + row) * K + (k0 + col));
            As[col + 0][row] = a4.x;
            As[col + 1][row] = a4.y;
            As[col + 2][row] = a4.z;
            As[col + 3][row] = a4.w;
        }

        if (!TRANS_B) {
            // B [K,N]: 16 rows x 128 cols
#pragma unroll
            for (int i = 0; i < 2; i++) {
                int idx  = tid + i * 256;
                int row  = idx >> 5;          // 0..15
                int col  = (idx & 31) * 4;    // 0..124
                float4 b4 = *reinterpret_cast<const float4*>(
                    Bb + (size_t)(k0 + row) * N + (bn + col));
                *reinterpret_cast<float4*>(&Bs[row][col]) = b4;
            }
        } else {
            // B [N,K] row-major; tile rows are output columns -> transpose like A
#pragma unroll
            for (int i = 0; i < 2; i++) {
                int idx  = tid + i * 256;
                int row  = idx >> 2;          // 0..127 (output column)
                int col  = (idx & 3) * 4;     // k offset
                float4 b4 = *reinterpret_cast<const float4*>(
                    Bb + (size_t)(bn + row) * K + (k0 + col));
                Bs[col + 0][row] = b4.x;
                Bs[col + 1][row] = b4.y;
                Bs[col + 2][row] = b4.z;
                Bs[col + 3][row] = b4.w;
            }
        }
        __syncthreads();

#pragma unroll
        for (int k = 0; k < BK; k++) {
            float af[TM], bf[TN];
#pragma unroll
            for (int i = 0; i < TM; i++) af[i] = As[k][ty * TM + i];
#pragma unroll
            for (int j = 0; j < TN; j++) bf[j] = Bs[k][tx * TN + j];
#pragma unroll
            for (int i = 0; i < TM; i++)
#pragma unroll
                for (int j = 0; j < TN; j++) acc[i][j] = fmaf(af[i], bf[j], acc[i][j]);
        }
        __syncthreads();
    }

#pragma unroll
    for (int i = 0; i < TM; i++) {
        size_t row = (size_t)(bm + ty * TM + i);
#pragma unroll
        for (int j = 0; j < TN; j += 4) {
            float4 v;
            v.x = acc[i][j + 0] * alpha;
            v.y = acc[i][j + 1] * alpha;
            v.z = acc[i][j + 2] * alpha;
            v.w = acc[i][j + 3] * alpha;
            *reinterpret_cast<float4*>(Cb + row * N + bn + tx * TN + j) = v;
        }
    }
}

// ---------------------------------------------------------------------------
// Row softmax over SEQ=4096 columns. One block (256 threads) per row.
// Row data lives entirely in registers (16 floats/thread).
// ---------------------------------------------------------------------------
__global__ __launch_bounds__(256)
void softmax_rows_kernel(float* __restrict__ S)
{
    __shared__ float red[8];
    const size_t row = blockIdx.x;
    float* p = S + row * (size_t)SEQ;
    const int tid = threadIdx.x;
    const int lane = tid & 31;
    const int warp = tid >> 5;

    float4 v[4];
    float m = -INFINITY;
#pragma unroll
    for (int i = 0; i < 4; i++) {
        v[i] = *reinterpret_cast<const float4*>(p + (size_t)(i * 256 + tid) * 4);
        m = fmaxf(m, fmaxf(fmaxf(v[i].x, v[i].y), fmaxf(v[i].z, v[i].w)));
    }
    // block max
#pragma unroll
    for (int o = 16; o > 0; o >>= 1) m = fmaxf(m, __shfl_xor_sync(0xffffffffu, m, o));
    if (lane == 0) red[warp] = m;
    __syncthreads();
    if (warp == 0) {
        float t = red[lane & 7];
#pragma unroll
        for (int o = 4; o > 0; o >>= 1) t = fmaxf(t, __shfl_xor_sync(0xffffffffu, t, o));
        if (lane == 0) red[0] = t;
    }
    __syncthreads();
    m = red[0];
    __syncthreads();

    float s = 0.0f;
#pragma unroll
    for (int i = 0; i < 4; i++) {
        v[i].x = __expf(v[i].x - m);
        v[i].y = __expf(v[i].y - m);
        v[i].z = __expf(v[i].z - m);
        v[i].w = __expf(v[i].w - m);
        s += (v[i].x + v[i].y) + (v[i].z + v[i].w);
    }
    // block sum
#pragma unroll
    for (int o = 16; o > 0; o >>= 1) s += __shfl_xor_sync(0xffffffffu, s, o);
    if (lane == 0) red[warp] = s;
    __syncthreads();
    if (warp == 0) {
        float t = red[lane & 7];
#pragma unroll
        for (int o = 4; o > 0; o >>= 1) t += __shfl_xor_sync(0xffffffffu, t, o);
        if (lane == 0) red[0] = t;
    }
    __syncthreads();
    const float inv = 1.0f / red[0];

#pragma unroll
    for (int i = 0; i < 4; i++) {
        float4 o4;
        o4.x = v[i].x * inv;
        o4.y = v[i].y * inv;
        o4.z = v[i].z * inv;
        o4.w = v[i].w * inv;
        *reinterpret_cast<float4*>(p + (size_t)(i * 256 + tid) * 4) = o4;
    }
}

// ---------------------------------------------------------------------------
extern "C" void kernel_launch(void* const* d_in, const int* in_sizes, int n_in,
                              void* d_out, int out_size)
{
    const float* x  = (const float*)d_in[0];   // [B, T, D]
    const float* QK = (const float*)d_in[1];   // [D, D]
    const float* VO = (const float*)d_in[2];   // [D, D]
    float* out = (float*)d_out;                // [B, T, D]

    float *xqk, *S, *av;
    cudaGetSymbolAddress((void**)&xqk, g_xQK);
    cudaGetSymbolAddress((void**)&S,   g_S);
    cudaGetSymbolAddress((void**)&av,  g_av);

    const size_t TD = (size_t)SEQ * D_MODEL;   // per-batch x / xQK / av stride
    const size_t TT = (size_t)SEQ * SEQ;       // per-batch scores stride
    const float scale = 1.0f / 32.0f;          // 1/sqrt(1024)

    // 1) xQK = x @ QK            [16384,1024] x [1024,1024]
    sgemm_kernel<false><<<dim3(D_MODEL / 128, (BATCH * SEQ) / 128, 1), 256>>>(
        BATCH * SEQ, D_MODEL, D_MODEL, 1.0f, x, 0, QK, 0, xqk, 0);

    // 2) S = (xQK @ x^T) / 32    per-batch [4096,1024] x [4096,1024]^T
    sgemm_kernel<true><<<dim3(SEQ / 128, SEQ / 128, BATCH), 256>>>(
        SEQ, SEQ, D_MODEL, scale, xqk, TD, x, TD, S, TT);

    // 3) P = softmax(S) rows (in place)
    softmax_rows_kernel<<<BATCH * SEQ, 256>>>(S);

    // 4) av = P @ x              per-batch [4096,4096] x [4096,1024]
    sgemm_kernel<false><<<dim3(D_MODEL / 128, SEQ / 128, BATCH), 256>>>(
        SEQ, D_MODEL, SEQ, 1.0f, S, TT, x, TD, av, TD);

    // 5) out = av @ VO           [16384,1024] x [1024,1024]
    sgemm_kernel<false><<<dim3(D_MODEL / 128, (BATCH * SEQ) / 128, 1), 256>>>(
        BATCH * SEQ, D_MODEL, D_MODEL, 1.0f, av, 0, VO, 0, out, 0);
}

// round 7
// speedup vs baseline: 2.5902x; 2.5902x over previous
#include <cuda_runtime.h>
#include <cuda_bf16.h>
#include <math.h>
#include <stdint.h>

#define D_MODEL 1024
#define BATCH   4
#define SEQ     4096

// ---------------------------------------------------------------------------
// Scratch (__device__ globals: allocation-free rule)
// ---------------------------------------------------------------------------
__device__ __align__(256) float g_S[(size_t)BATCH * SEQ * SEQ];                      // 256 MB

__device__ __align__(256) __nv_bfloat16 g_xh  [(size_t)BATCH * SEQ * D_MODEL];
__device__ __align__(256) __nv_bfloat16 g_xl  [(size_t)BATCH * SEQ * D_MODEL];
__device__ __align__(256) __nv_bfloat16 g_xth [(size_t)BATCH * D_MODEL * SEQ];       // x^T per batch
__device__ __align__(256) __nv_bfloat16 g_xtl [(size_t)BATCH * D_MODEL * SEQ];
__device__ __align__(256) __nv_bfloat16 g_QKth[(size_t)D_MODEL * D_MODEL];
__device__ __align__(256) __nv_bfloat16 g_QKtl[(size_t)D_MODEL * D_MODEL];
__device__ __align__(256) __nv_bfloat16 g_VOth[(size_t)D_MODEL * D_MODEL];
__device__ __align__(256) __nv_bfloat16 g_VOtl[(size_t)D_MODEL * D_MODEL];
__device__ __align__(256) __nv_bfloat16 g_xqkh[(size_t)BATCH * SEQ * D_MODEL];
__device__ __align__(256) __nv_bfloat16 g_xqkl[(size_t)BATCH * SEQ * D_MODEL];
__device__ __align__(256) __nv_bfloat16 g_Ph  [(size_t)BATCH * SEQ * SEQ];           // 128 MB
__device__ __align__(256) __nv_bfloat16 g_Pl  [(size_t)BATCH * SEQ * SEQ];           // 128 MB
__device__ __align__(256) __nv_bfloat16 g_avh [(size_t)BATCH * SEQ * D_MODEL];
__device__ __align__(256) __nv_bfloat16 g_avl [(size_t)BATCH * SEQ * D_MODEL];

// ---------------------------------------------------------------------------
// Helpers
// ---------------------------------------------------------------------------
__device__ __forceinline__ uint32_t smem_u32(const void* p) {
    uint32_t a;
    asm("{ .reg .u64 t; cvta.to.shared.u64 t, %1; cvt.u32.u64 %0, t; }" : "=r"(a) : "l"(p));
    return a;
}
__device__ __forceinline__ void cp16(uint32_t dst, const void* src) {
    asm volatile("cp.async.cg.shared.global [%0], [%1], 16;"
        :: "r"(dst), "l"(__cvta_generic_to_global(src)) : "memory");
}
#define CP_COMMIT() asm volatile("cp.async.commit_group;" ::: "memory")

__device__ __forceinline__ void ldsm_x4(uint32_t addr, uint32_t& r0, uint32_t& r1,
                                        uint32_t& r2, uint32_t& r3) {
    asm volatile("ldmatrix.sync.aligned.m8n8.x4.shared.b16 {%0,%1,%2,%3}, [%4];"
        : "=r"(r0), "=r"(r1), "=r"(r2), "=r"(r3) : "r"(addr));
}
__device__ __forceinline__ void mma_bf16(float* d, const uint32_t* a, uint32_t b0, uint32_t b1) {
    asm volatile(
        "mma.sync.aligned.m16n8k16.row.col.f32.bf16.bf16.f32 "
        "{%0,%1,%2,%3}, {%4,%5,%6,%7}, {%8,%9}, {%0,%1,%2,%3};"
        : "+f"(d[0]), "+f"(d[1]), "+f"(d[2]), "+f"(d[3])
        : "r"(a[0]), "r"(a[1]), "r"(a[2]), "r"(a[3]), "r"(b0), "r"(b1));
}
__device__ __forceinline__ void split2(float v, __nv_bfloat16& h, __nv_bfloat16& l) {
    h = __float2bfloat16(v);
    l = __float2bfloat16(v - __bfloat162float(h));
}

// ---------------------------------------------------------------------------
// Conversion kernels
// ---------------------------------------------------------------------------
__global__ __launch_bounds__(256)
void split_kernel(const float* __restrict__ in, __nv_bfloat16* __restrict__ hi,
                  __nv_bfloat16* __restrict__ lo, size_t n)
{
    size_t i = ((size_t)blockIdx.x * 256 + threadIdx.x) * 4;
    if (i >= n) return;
    float4 v = *reinterpret_cast<const float4*>(in + i);
    __nv_bfloat16 h0, h1, h2, h3, l0, l1, l2, l3;
    split2(v.x, h0, l0); split2(v.y, h1, l1); split2(v.z, h2, l2); split2(v.w, h3, l3);
    *reinterpret_cast<__nv_bfloat162*>(hi + i)     = __nv_bfloat162(h0, h1);
    *reinterpret_cast<__nv_bfloat162*>(hi + i + 2) = __nv_bfloat162(h2, h3);
    *reinterpret_cast<__nv_bfloat162*>(lo + i)     = __nv_bfloat162(l0, l1);
    *reinterpret_cast<__nv_bfloat162*>(lo + i + 2) = __nv_bfloat162(l2, l3);
}

// Transposed split: out[c][r] = in[r][c], per batch z. in: [R,C], out planes: [C,R].
__global__ __launch_bounds__(256)
void transpose_split_kernel(const float* __restrict__ in, __nv_bfloat16* __restrict__ hi,
                            __nv_bfloat16* __restrict__ lo, int R, int C)
{
    __shared__ float t[32][33];
    const size_t zoff = (size_t)blockIdx.z * R * C;
    const float* ib = in + zoff;
    const int r0 = blockIdx.y * 32, c0 = blockIdx.x * 32;
    const int tx = threadIdx.x, ty = threadIdx.y;   // 32 x 8
#pragma unroll
    for (int i = 0; i < 32; i += 8)
        t[ty + i][tx] = ib[(size_t)(r0 + ty + i) * C + c0 + tx];
    __syncthreads();
#pragma unroll
    for (int i = 0; i < 32; i += 8) {
        float v = t[tx][ty + i];
        size_t o = zoff + (size_t)(c0 + ty + i) * R + r0 + tx;
        __nv_bfloat16 h, l;
        split2(v, h, l);
        hi[o] = h;
        lo[o] = l;
    }
}

// ---------------------------------------------------------------------------
// mma.sync split-bf16 NT GEMM: D[m][n] = alpha * sum_k (Ah+Al)[m][k]*(Bh+Bl)[n][k]
//   3 passes (Ah*Bh, Ah*Bl, Al*Bh), fp32 accumulate in registers.
//   BM=BN=128, BK=64 (128B rows, SW128 XOR swizzle), 3-stage cp.async pipeline.
//   8 warps = 4(m) x 2(n); warp tile 32x64; atoms m16n8k16.
//   EPI=0: fp32 out.  EPI=1: hi/lo bf16 planes out.
// ---------------------------------------------------------------------------
#define GBM 128
#define GBN 128
#define GBK 64
#define NSTAGE 3
#define TILE_BYTES 16384
#define GEMM_SMEM (2 * NSTAGE * TILE_BYTES)

template <int EPI>
__global__ __launch_bounds__(256)
void gemm_nt_mma(int M, int N, int K, float alpha,
                 const __nv_bfloat16* __restrict__ Ah, const __nv_bfloat16* __restrict__ Al, size_t sA,
                 const __nv_bfloat16* __restrict__ Bh, const __nv_bfloat16* __restrict__ Bl, size_t sB,
                 float* __restrict__ Cf, __nv_bfloat16* __restrict__ Ch, __nv_bfloat16* __restrict__ Cl,
                 size_t sC)
{
    extern __shared__ __align__(128) char sm[];
    const uint32_t smbase = smem_u32(sm);

    const int tid = threadIdx.x, lane = tid & 31, wid = tid >> 5;
    const int wm = wid & 3, wn = wid >> 2;            // 4 x 2 warp grid
    const int bm = blockIdx.y * GBM, bn = blockIdx.x * GBN;
    const size_t z = blockIdx.z;

    const int KT = K / GBK;
    const int NIT = 3 * KT;                           // >= 48 for all our shapes

    const __nv_bfloat16* Aplane[3] = { Ah, Ah, Al };
    const __nv_bfloat16* Bplane[3] = { Bh, Bl, Bh };

    auto issue = [&](int it, int buf) {
        const int s = it / KT, kt = it - s * KT;
        const __nv_bfloat16* As = Aplane[s] + z * sA + (size_t)bm * K + kt * GBK;
        const __nv_bfloat16* Bs = Bplane[s] + z * sB + (size_t)bn * K + kt * GBK;
        const uint32_t da = smbase + buf * TILE_BYTES;
        const uint32_t db = smbase + NSTAGE * TILE_BYTES + buf * TILE_BYTES;
#pragma unroll
        for (int i = 0; i < 4; i++) {
            int c   = tid + i * 256;
            int row = c >> 3;            // 0..127
            int ck  = c & 7;             // 16B chunk within 128B row
            uint32_t off = (uint32_t)(row * 128 + ((ck * 16) ^ ((row & 7) << 4)));
            cp16(da + off, As + (size_t)row * K + ck * 8);
            cp16(db + off, Bs + (size_t)row * K + ck * 8);
        }
        CP_COMMIT();
    };

    float d[2][8][4];
#pragma unroll
    for (int am = 0; am < 2; am++)
#pragma unroll
        for (int an = 0; an < 8; an++)
#pragma unroll
            for (int q = 0; q < 4; q++) d[am][an][q] = 0.0f;

    issue(0, 0);
    issue(1, 1);
    issue(2, 2);

    const int lrow = lane & 15;
    const int lcol = (lane >> 4) * 16;   // byte offset of 8-half group

    int buf = 0;
    for (int it = 0; it < NIT; it++) {
        // Retire the group that fills buffer `buf` (tail-aware wait count).
        if (it + 3 <= NIT)      asm volatile("cp.async.wait_group 2;" ::: "memory");
        else if (it + 2 == NIT) asm volatile("cp.async.wait_group 1;" ::: "memory");
        else                    asm volatile("cp.async.wait_group 0;" ::: "memory");
        __syncthreads();

        const uint32_t Aa = smbase + buf * TILE_BYTES;
        const uint32_t Ba = smbase + NSTAGE * TILE_BYTES + buf * TILE_BYTES;

#pragma unroll
        for (int kk = 0; kk < 4; kk++) {
            const int colb = kk * 32 + lcol;
            uint32_t a[2][4], b[4][4];
#pragma unroll
            for (int am = 0; am < 2; am++) {
                int row = wm * 32 + am * 16 + lrow;
                uint32_t off = (uint32_t)(row * 128 + (colb ^ ((row & 7) << 4)));
                ldsm_x4(Aa + off, a[am][0], a[am][1], a[am][2], a[am][3]);
            }
#pragma unroll
            for (int nb = 0; nb < 4; nb++) {
                int row = wn * 64 + nb * 16 + lrow;
                uint32_t off = (uint32_t)(row * 128 + (colb ^ ((row & 7) << 4)));
                ldsm_x4(Ba + off, b[nb][0], b[nb][1], b[nb][2], b[nb][3]);
            }
#pragma unroll
            for (int am = 0; am < 2; am++)
#pragma unroll
                for (int an = 0; an < 8; an++)
                    mma_bf16(d[am][an], a[am], b[an >> 1][an & 1], b[an >> 1][(an & 1) + 2]);
        }
        __syncthreads();
        if (it + NSTAGE < NIT) issue(it + NSTAGE, buf);
        buf = (buf == NSTAGE - 1) ? 0 : buf + 1;
    }

    // Epilogue: per-atom store. c0,c1 at (row, col..col+1); c2,c3 at (row+8, ...).
    const int er = lane >> 2;
    const int ec = (lane & 3) * 2;
#pragma unroll
    for (int am = 0; am < 2; am++) {
#pragma unroll
        for (int an = 0; an < 8; an++) {
            const int row = bm + wm * 32 + am * 16 + er;
            const int col = bn + wn * 64 + an * 8 + ec;
            const float v0 = d[am][an][0] * alpha;
            const float v1 = d[am][an][1] * alpha;
            const float v2 = d[am][an][2] * alpha;
            const float v3 = d[am][an][3] * alpha;
            const size_t o0 = z * sC + (size_t)row * N + col;
            const size_t o1 = z * sC + (size_t)(row + 8) * N + col;
            if (EPI == 0) {
                *reinterpret_cast<float2*>(Cf + o0) = make_float2(v0, v1);
                *reinterpret_cast<float2*>(Cf + o1) = make_float2(v2, v3);
            } else {
                __nv_bfloat16 h0, l0, h1, l1;
                split2(v0, h0, l0); split2(v1, h1, l1);
                *reinterpret_cast<__nv_bfloat162*>(Ch + o0) = __nv_bfloat162(h0, h1);
                *reinterpret_cast<__nv_bfloat162*>(Cl + o0) = __nv_bfloat162(l0, l1);
                split2(v2, h0, l0); split2(v3, h1, l1);
                *reinterpret_cast<__nv_bfloat162*>(Ch + o1) = __nv_bfloat162(h0, h1);
                *reinterpret_cast<__nv_bfloat162*>(Cl + o1) = __nv_bfloat162(l0, l1);
            }
        }
    }
}

// ---------------------------------------------------------------------------
// Row softmax over SEQ=4096: reads fp32 S, writes split bf16 P (hi/lo planes)
// ---------------------------------------------------------------------------
__global__ __launch_bounds__(256)
void softmax_split_kernel(const float* __restrict__ S,
                          __nv_bfloat16* __restrict__ Ph, __nv_bfloat16* __restrict__ Pl)
{
    __shared__ float red[8];
    const size_t row = blockIdx.x;
    const float* p = S + row * (size_t)SEQ;
    const int tid = threadIdx.x, lane = tid & 31, warp = tid >> 5;

    float4 v[4];
    float m = -INFINITY;
#pragma unroll
    for (int i = 0; i < 4; i++) {
        v[i] = *reinterpret_cast<const float4*>(p + (size_t)(i * 256 + tid) * 4);
        m = fmaxf(m, fmaxf(fmaxf(v[i].x, v[i].y), fmaxf(v[i].z, v[i].w)));
    }
#pragma unroll
    for (int o = 16; o > 0; o >>= 1) m = fmaxf(m, __shfl_xor_sync(0xffffffffu, m, o));
    if (lane == 0) red[warp] = m;
    __syncthreads();
    if (warp == 0) {
        float t = red[lane & 7];
#pragma unroll
        for (int o = 4; o > 0; o >>= 1) t = fmaxf(t, __shfl_xor_sync(0xffffffffu, t, o));
        if (lane == 0) red[0] = t;
    }
    __syncthreads();
    m = red[0];
    __syncthreads();

    float s = 0.0f;
#pragma unroll
    for (int i = 0; i < 4; i++) {
        v[i].x = __expf(v[i].x - m);
        v[i].y = __expf(v[i].y - m);
        v[i].z = __expf(v[i].z - m);
        v[i].w = __expf(v[i].w - m);
        s += (v[i].x + v[i].y) + (v[i].z + v[i].w);
    }
#pragma unroll
    for (int o = 16; o > 0; o >>= 1) s += __shfl_xor_sync(0xffffffffu, s, o);
    if (lane == 0) red[warp] = s;
    __syncthreads();
    if (warp == 0) {
        float t = red[lane & 7];
#pragma unroll
        for (int o = 4; o > 0; o >>= 1) t += __shfl_xor_sync(0xffffffffu, t, o);
        if (lane == 0) red[0] = t;
    }
    __syncthreads();
    const float inv = 1.0f / red[0];

    const size_t rb = row * (size_t)SEQ;
#pragma unroll
    for (int i = 0; i < 4; i++) {
        size_t idx = rb + (size_t)(i * 256 + tid) * 4;
        __nv_bfloat16 h0, h1, h2, h3, l0, l1, l2, l3;
        split2(v[i].x * inv, h0, l0);
        split2(v[i].y * inv, h1, l1);
        split2(v[i].z * inv, h2, l2);
        split2(v[i].w * inv, h3, l3);
        *reinterpret_cast<__nv_bfloat162*>(Ph + idx)     = __nv_bfloat162(h0, h1);
        *reinterpret_cast<__nv_bfloat162*>(Ph + idx + 2) = __nv_bfloat162(h2, h3);
        *reinterpret_cast<__nv_bfloat162*>(Pl + idx)     = __nv_bfloat162(l0, l1);
        *reinterpret_cast<__nv_bfloat162*>(Pl + idx + 2) = __nv_bfloat162(l2, l3);
    }
}

// ---------------------------------------------------------------------------
extern "C" void kernel_launch(void* const* d_in, const int* in_sizes, int n_in,
                              void* d_out, int out_size)
{
    const float* x  = (const float*)d_in[0];   // [B, T, D]
    const float* QK = (const float*)d_in[1];   // [D, D]
    const float* VO = (const float*)d_in[2];   // [D, D]
    float* out = (float*)d_out;                // [B, T, D]

    float* S;
    __nv_bfloat16 *xh, *xl, *xth, *xtl, *qkh, *qkl, *voh, *vol;
    __nv_bfloat16 *xqkh, *xqkl, *Ph, *Pl, *avh, *avl;
    cudaGetSymbolAddress((void**)&S,    g_S);
    cudaGetSymbolAddress((void**)&xh,   g_xh);
    cudaGetSymbolAddress((void**)&xl,   g_xl);
    cudaGetSymbolAddress((void**)&xth,  g_xth);
    cudaGetSymbolAddress((void**)&xtl,  g_xtl);
    cudaGetSymbolAddress((void**)&qkh,  g_QKth);
    cudaGetSymbolAddress((void**)&qkl,  g_QKtl);
    cudaGetSymbolAddress((void**)&voh,  g_VOth);
    cudaGetSymbolAddress((void**)&vol,  g_VOtl);
    cudaGetSymbolAddress((void**)&xqkh, g_xqkh);
    cudaGetSymbolAddress((void**)&xqkl, g_xqkl);
    cudaGetSymbolAddress((void**)&Ph,   g_Ph);
    cudaGetSymbolAddress((void**)&Pl,   g_Pl);
    cudaGetSymbolAddress((void**)&avh,  g_avh);
    cudaGetSymbolAddress((void**)&avl,  g_avl);

    cudaFuncSetAttribute(gemm_nt_mma<0>, cudaFuncAttributeMaxDynamicSharedMemorySize, GEMM_SMEM);
    cudaFuncSetAttribute(gemm_nt_mma<1>, cudaFuncAttributeMaxDynamicSharedMemorySize, GEMM_SMEM);

    const size_t nx = (size_t)BATCH * SEQ * D_MODEL;   // 16M
    const size_t TD = (size_t)SEQ * D_MODEL;
    const size_t DT = (size_t)D_MODEL * SEQ;
    const size_t TT = (size_t)SEQ * SEQ;
    const float scale = 1.0f / 32.0f;                  // 1/sqrt(1024)

    // ---- conversions ----
    split_kernel<<<(unsigned)(nx / 1024), 256>>>(x, xh, xl, nx);
    transpose_split_kernel<<<dim3(D_MODEL / 32, D_MODEL / 32, 1), dim3(32, 8)>>>(QK, qkh, qkl, D_MODEL, D_MODEL);
    transpose_split_kernel<<<dim3(D_MODEL / 32, D_MODEL / 32, 1), dim3(32, 8)>>>(VO, voh, vol, D_MODEL, D_MODEL);
    transpose_split_kernel<<<dim3(D_MODEL / 32, SEQ / 32, BATCH), dim3(32, 8)>>>(x, xth, xtl, SEQ, D_MODEL);

    // ---- 1) xQK = x @ QK : NT vs QK^T -> split planes
    gemm_nt_mma<1><<<dim3(D_MODEL / GBN, (BATCH * SEQ) / GBM, 1), 256, GEMM_SMEM>>>(
        BATCH * SEQ, D_MODEL, D_MODEL, 1.0f,
        xh, xl, 0, qkh, qkl, 0, nullptr, xqkh, xqkl, 0);

    // ---- 2) S = (xQK @ x^T)/32 : NT per batch -> fp32
    gemm_nt_mma<0><<<dim3(SEQ / GBN, SEQ / GBM, BATCH), 256, GEMM_SMEM>>>(
        SEQ, SEQ, D_MODEL, scale,
        xqkh, xqkl, TD, xh, xl, TD, S, nullptr, nullptr, TT);

    // ---- 3) P = softmax(S) -> split planes
    softmax_split_kernel<<<BATCH * SEQ, 256>>>(S, Ph, Pl);

    // ---- 4) av = P @ x : NT vs x^T per batch -> split planes
    gemm_nt_mma<1><<<dim3(D_MODEL / GBN, SEQ / GBM, BATCH), 256, GEMM_SMEM>>>(
        SEQ, D_MODEL, SEQ, 1.0f,
        Ph, Pl, TT, xth, xtl, DT, nullptr, avh, avl, TD);

    // ---- 5) out = av @ VO : NT vs VO^T -> fp32
    gemm_nt_mma<0><<<dim3(D_MODEL / GBN, (BATCH * SEQ) / GBM, 1), 256, GEMM_SMEM>>>(
        BATCH * SEQ, D_MODEL, D_MODEL, 1.0f,
        avh, avl, 0, voh, vol, 0, out, nullptr, nullptr, TD);
}